// round 12
// baseline (speedup 1.0000x reference)
#include <cuda_runtime.h>
#include <math.h>

#define B_    2
#define CIN   32
#define COUT  32
#define D_    40
#define E_    3
#define SP    (D_*D_*D_)          // 64000
#define YTOT  (B_*COUT*SP)        // 4,096,000
#define OCG   4
#define NOCG  (COUT/OCG)          // 8
#define ZT    2
#define YT    8
#define SROW  48
#define NROWS ((ZT+2)*(YT+2))     // 40 rows
#define SLABVOL (NROWS*SROW)      // 1920 floats
#define UBLK  (CIN*3*16*OCG)      // 6144 floats per (b,ocg) of transformed U
#define NTHR  160

// ---- scratch (device globals; no runtime allocation) ----
__device__ float g_u[B_*NOCG*UBLK];     // [b][ocg][ic][dz][pos16][oc4]
__device__ float g_bias[B_*COUT];
__device__ float g_y[YTOT];
__device__ float g_sum[COUT];
__device__ float g_sumsq[COUT];
__device__ float g_scale[COUT];
__device__ float g_shift[COUT];

// ---------------------------------------------------------------------------
// Kernel 1: routing + Winograd-transformed weights U = G g G^T per (oc,ic,dz)
// ---------------------------------------------------------------------------
__global__ void k_route(const float* __restrict__ emb,
                        const float* __restrict__ rw,
                        const float* __restrict__ rb,
                        const float* __restrict__ ek,
                        const float* __restrict__ eb) {
    float r[B_][E_];
    #pragma unroll
    for (int b = 0; b < B_; b++)
        #pragma unroll
        for (int e = 0; e < E_; e++) {
            float t = fmaf(emb[b], rw[e], rb[e]);
            r[b][e] = 1.0f / (1.0f + expf(-t));
        }

    int idx = blockIdx.x * blockDim.x + threadIdx.x;
    const int TOT = B_ * NOCG * CIN * 3 * OCG;   // 6144 threads: one (b,ocg,ic,dz,og)
    if (idx < TOT) {
        int rr = idx;
        int og = rr & 3;          rr >>= 2;
        int dz = rr % 3;          rr /= 3;
        int ic = rr % CIN;        rr /= CIN;
        int ocg = rr % NOCG;
        int b   = rr / NOCG;
        int oc  = ocg * OCG + og;

        // combined 3x3 slice for this dz
        float g[3][3];
        #pragma unroll
        for (int ky = 0; ky < 3; ky++)
            #pragma unroll
            for (int kx = 0; kx < 3; kx++) {
                float s = 0.0f;
                #pragma unroll
                for (int e = 0; e < E_; e++)
                    s = fmaf(r[b][e],
                             ek[((e * COUT + oc) * CIN + ic) * 27 + dz * 9 + ky * 3 + kx], s);
                g[ky][kx] = s;
            }
        // T = G g  (y-transform), 4x3
        float T[4][3];
        #pragma unroll
        for (int kx = 0; kx < 3; kx++) {
            T[0][kx] = g[0][kx];
            T[1][kx] = 0.5f * (g[0][kx] + g[1][kx] + g[2][kx]);
            T[2][kx] = 0.5f * (g[0][kx] - g[1][kx] + g[2][kx]);
            T[3][kx] = g[2][kx];
        }
        // U = T G^T (x-transform), 4x4; store [pos][oc4]
        float* dst = g_u + (size_t)(b * NOCG + ocg) * UBLK + (ic * 3 + dz) * 16 * OCG + og;
        #pragma unroll
        for (int i = 0; i < 4; i++) {
            float u0 = T[i][0];
            float u1 = 0.5f * (T[i][0] + T[i][1] + T[i][2]);
            float u2 = 0.5f * (T[i][0] - T[i][1] + T[i][2]);
            float u3 = T[i][2];
            dst[(i * 4 + 0) * 4] = u0;
            dst[(i * 4 + 1) * 4] = u1;
            dst[(i * 4 + 2) * 4] = u2;
            dst[(i * 4 + 3) * 4] = u3;
        }
    }
    if (idx < B_ * COUT) {
        int b = idx / COUT, o = idx - b * COUT;
        float s = 0.0f;
        #pragma unroll
        for (int e = 0; e < E_; e++) s = fmaf(r[b][e], eb[e * COUT + o], s);
        g_bias[idx] = s;
    }
    if (idx < COUT) { g_sum[idx] = 0.0f; g_sumsq[idx] = 0.0f; }
}

// ---------------------------------------------------------------------------
// Kernel 2: Winograd F(2x2,3x3) in (y,x), direct z. 4 oc per block.
// 160 thr = 2z x 4 ytiles x 20 xtiles, one 2x2 tile per thread, m[4][16] acc.
// grid = (100, 8, 2)
// ---------------------------------------------------------------------------
__global__ void __launch_bounds__(NTHR, 3)
k_conv(const float* __restrict__ x) {
    extern __shared__ float dyn[];
    float* sh  = dyn;                    // [2][SLABVOL]
    float* ush = dyn + 2 * SLABVOL;      // [UBLK]
    float* red = ush + UBLK;             // [48]

    const int zt  = blockIdx.x / 5;
    const int yt  = blockIdx.x - 5 * zt;
    const int z0  = zt * ZT;
    const int y0  = yt * YT;
    const int ocg = blockIdx.y;
    const int b   = blockIdx.z;
    const int t   = threadIdx.x;

    for (int i = t; i < 2 * SLABVOL; i += NTHR) dyn[i] = 0.0f;
    const float* gu = g_u + (size_t)(b * NOCG + ocg) * UBLK;
    for (int i = t; i < UBLK; i += NTHR) ush[i] = gu[i];

    // ---- loader: 2 threads per row (t < 80), 5 x 16B cp.async each ----
    const float* xb = x + (size_t)(b * CIN) * SP;
    const int lrow = t >> 1;
    const int half = t & 1;
    const int lz = lrow / 10, ly2 = lrow - 10 * (lrow / 10);
    const int gz = z0 - 1 + lz, gy = y0 - 1 + ly2;
    const bool rowok = (t < 80) && ((unsigned)gz < D_) && ((unsigned)gy < D_);
    const long grow = (long)gz * 1600 + (long)gy * 40 + 20 * half;
    const unsigned sdst0 = (unsigned)__cvta_generic_to_shared(sh)
                         + (unsigned)(lrow * (SROW * 4) + 16 + 80 * half);

    auto prefetch = [&](int ic, int buf) {
        if (!rowok) return;
        const float* src = xb + (size_t)ic * SP + grow;
        unsigned d = sdst0 + (unsigned)buf * (SLABVOL * 4);
        #pragma unroll
        for (int c = 0; c < 5; c++)
            asm volatile("cp.async.cg.shared.global [%0], [%1], 16;"
                         :: "r"(d + c * 16), "l"(src + c * 4));
    };

    // ---- compute setup ----
    const int xt  = t % 20;              // x-tile: outputs 2xt, 2xt+1
    const int lyt = (t / 20) % 4;        // y-tile: outputs y0+2lyt, +1
    const int tz  = t / 80;              // local z

    float m[OCG][16];
    #pragma unroll
    for (int og = 0; og < OCG; og++)
        #pragma unroll
        for (int p = 0; p < 16; p++) m[og][p] = 0.0f;

    __syncthreads();
    prefetch(0, 0);
    asm volatile("cp.async.commit_group;");

    const int wbase = 2 + 2 * xt;        // even word; patch words wbase+1..wbase+4

    for (int ic = 0; ic < CIN; ic++) {
        __syncthreads();
        if (ic + 1 < CIN) prefetch(ic + 1, (ic + 1) & 1);
        asm volatile("cp.async.commit_group;");
        asm volatile("cp.async.wait_group 1;");
        __syncthreads();

        const float* S = sh + (ic & 1) * SLABVOL;
        const float4* U4 = (const float4*)ush;
        #pragma unroll 1
        for (int dz = 0; dz < 3; dz++) {
            // load 4x4 patch: rows 2*lyt+i in z-plane (tz+dz)
            float d0[4], d1[4], d2[4], d3[4];   // d_i[j]: row i, col j
            {
                const int rb0 = ((tz + dz) * 10 + 2 * lyt) * SROW + wbase;
                #pragma unroll
                for (int i = 0; i < 4; i++) {
                    const float* rp = S + rb0 + i * SROW;
                    float2 a = *(const float2*)(rp);
                    float2 bq = *(const float2*)(rp + 2);
                    float2 c = *(const float2*)(rp + 4);
                    d0[i] = a.y; d1[i] = bq.x; d2[i] = bq.y; d3[i] = c.x;
                }
                // note: d{j}[i] holds row i, col j  (col-major temp)
            }
            // y-transform (over rows i): c_k[j]
            float c0[4], c1[4], c2[4], c3[4];
            #pragma unroll
            for (int j = 0; j < 4; j++) {
                float e0, e1, e2, e3;
                switch (j) {
                    case 0: e0 = d0[0]; e1 = d0[1]; e2 = d0[2]; e3 = d0[3]; break;
                    case 1: e0 = d1[0]; e1 = d1[1]; e2 = d1[2]; e3 = d1[3]; break;
                    case 2: e0 = d2[0]; e1 = d2[1]; e2 = d2[2]; e3 = d2[3]; break;
                    default: e0 = d3[0]; e1 = d3[1]; e2 = d3[2]; e3 = d3[3]; break;
                }
                c0[j] = e0 - e2;
                c1[j] = e1 + e2;
                c2[j] = e2 - e1;
                c3[j] = e1 - e3;
            }
            // x-transform (over cols j): V[k][l], flat pos = k*4+l
            float v[16];
            #pragma unroll
            for (int k = 0; k < 4; k++) {
                float e0, e1, e2, e3;
                switch (k) {
                    case 0: e0 = c0[0]; e1 = c0[1]; e2 = c0[2]; e3 = c0[3]; break;
                    case 1: e0 = c1[0]; e1 = c1[1]; e2 = c1[2]; e3 = c1[3]; break;
                    case 2: e0 = c2[0]; e1 = c2[1]; e2 = c2[2]; e3 = c2[3]; break;
                    default: e0 = c3[0]; e1 = c3[1]; e2 = c3[2]; e3 = c3[3]; break;
                }
                v[k * 4 + 0] = e0 - e2;
                v[k * 4 + 1] = e1 + e2;
                v[k * 4 + 2] = e2 - e1;
                v[k * 4 + 3] = e1 - e3;
            }
            // accumulate: m[og][p] += U[p][og] * v[p]
            const float4* Up = U4 + (ic * 3 + dz) * 16;
            #pragma unroll
            for (int p = 0; p < 16; p++) {
                float4 w4 = Up[p];
                m[0][p] = fmaf(w4.x, v[p], m[0][p]);
                m[1][p] = fmaf(w4.y, v[p], m[1][p]);
                m[2][p] = fmaf(w4.z, v[p], m[2][p]);
                m[3][p] = fmaf(w4.w, v[p], m[3][p]);
            }
        }
    }

    // ---- epilogue: inverse transform A^T M A, bias, store, BN sums ----
    float s1[OCG], s2[OCG];
    #pragma unroll
    for (int og = 0; og < OCG; og++) { s1[og] = 0.0f; s2[og] = 0.0f; }

    {
        const int zo = z0 + tz, yo = y0 + 2 * lyt, xo = 2 * xt;
        #pragma unroll
        for (int og = 0; og < OCG; og++) {
            const int oc = ocg * OCG + og;
            const float bias = g_bias[b * COUT + oc];
            float r0[4], r1[4];
            #pragma unroll
            for (int j = 0; j < 4; j++) {
                r0[j] = m[og][0 * 4 + j] + m[og][1 * 4 + j] + m[og][2 * 4 + j];
                r1[j] = m[og][1 * 4 + j] - m[og][2 * 4 + j] - m[og][3 * 4 + j];
            }
            float y00 = r0[0] + r0[1] + r0[2] + bias;
            float y01 = r0[1] - r0[2] - r0[3] + bias;
            float y10 = r1[0] + r1[1] + r1[2] + bias;
            float y11 = r1[1] - r1[2] - r1[3] + bias;
            s1[og] += y00 + y01 + y10 + y11;
            s2[og] = fmaf(y00, y00, s2[og]);
            s2[og] = fmaf(y01, y01, s2[og]);
            s2[og] = fmaf(y10, y10, s2[og]);
            s2[og] = fmaf(y11, y11, s2[og]);
            float* yp = g_y + (size_t)(b * COUT + oc) * SP + zo * 1600 + yo * 40 + xo;
            *(float2*)yp        = make_float2(y00, y01);
            *(float2*)(yp + 40) = make_float2(y10, y11);
        }
    }
    #pragma unroll
    for (int og = 0; og < OCG; og++) {
        #pragma unroll
        for (int o = 16; o > 0; o >>= 1) {
            s1[og] += __shfl_down_sync(0xffffffff, s1[og], o);
            s2[og] += __shfl_down_sync(0xffffffff, s2[og], o);
        }
    }
    const int wid = t >> 5, lane = t & 31;    // 5 warps
    __syncthreads();
    if (lane == 0) {
        #pragma unroll
        for (int og = 0; og < OCG; og++) {
            red[og * 5 + wid]      = s1[og];
            red[24 + og * 5 + wid] = s2[og];
        }
    }
    __syncthreads();
    if (t < OCG) {
        float a = 0.0f, q = 0.0f;
        #pragma unroll
        for (int i = 0; i < 5; i++) { a += red[t * 5 + i]; q += red[24 + t * 5 + i]; }
        atomicAdd(&g_sum[ocg * OCG + t], a);
        atomicAdd(&g_sumsq[ocg * OCG + t], q);
    }
}

// ---------------------------------------------------------------------------
// Kernel 3: finalize BN -> per-channel scale/shift
// ---------------------------------------------------------------------------
__global__ void k_stats(const float* __restrict__ gamma,
                        const float* __restrict__ beta) {
    int c = threadIdx.x;
    if (c < COUT) {
        const float n = (float)(B_ * SP);
        float mean = g_sum[c] / n;
        float var  = g_sumsq[c] / n - mean * mean;
        float sc = gamma[c] * rsqrtf(var + 1e-5f);
        g_scale[c] = sc;
        g_shift[c] = beta[c] - mean * sc;
    }
}

// ---------------------------------------------------------------------------
// Kernel 4: affine + LeakyReLU + nearest upsample x2
// ---------------------------------------------------------------------------
__global__ void __launch_bounds__(256)
k_up(float* __restrict__ out) {
    int idx = blockIdx.x * blockDim.x + threadIdx.x;
    if (idx >= YTOT / 2) return;
    int i2 = idx * 2;
    int xw = i2 % 40;
    int rest = i2 / 40;
    int yw = rest % 40; rest /= 40;
    int zw = rest % 40; rest /= 40;
    int c  = rest % COUT;
    int b  = rest / COUT;

    float2 v = *(const float2*)&g_y[i2];
    float sc = g_scale[c], sf = g_shift[c];
    float a0 = fmaf(sc, v.x, sf); a0 = (a0 >= 0.0f) ? a0 : 0.1f * a0;
    float a1 = fmaf(sc, v.y, sf); a1 = (a1 >= 0.0f) ? a1 : 0.1f * a1;
    float4 p = make_float4(a0, a0, a1, a1);

    size_t base = ((size_t)(b * COUT + c) * 512000u)
                + (size_t)(2 * zw) * 6400u + (size_t)(2 * yw) * 80u + (size_t)(2 * xw);
    float4* o4 = (float4*)(out + base);
    o4[0]    = p;
    o4[20]   = p;
    o4[1600] = p;
    o4[1620] = p;
}

// ---------------------------------------------------------------------------
extern "C" void kernel_launch(void* const* d_in, const int* in_sizes, int n_in,
                              void* d_out, int out_size) {
    const float* x     = (const float*)d_in[0];
    const float* emb   = (const float*)d_in[1];
    const float* rw    = (const float*)d_in[2];
    const float* rb    = (const float*)d_in[3];
    const float* ek    = (const float*)d_in[4];
    const float* eb    = (const float*)d_in[5];
    const float* gamma = (const float*)d_in[6];
    const float* beta  = (const float*)d_in[7];
    float* out = (float*)d_out;

    k_route<<<(B_ * NOCG * CIN * 3 * OCG + 255) / 256, 256>>>(emb, rw, rb, ek, eb);

    size_t shbytes = (size_t)(2 * SLABVOL + UBLK + 48) * sizeof(float);  // ~40 KB
    cudaFuncSetAttribute(k_conv, cudaFuncAttributeMaxDynamicSharedMemorySize, (int)shbytes);
    dim3 gconv(100, NOCG, B_);
    k_conv<<<gconv, NTHR, shbytes>>>(x);

    k_stats<<<1, 32>>>(gamma, beta);

    k_up<<<(YTOT / 2 + 255) / 256, 256>>>(out);
}